// round 6
// baseline (speedup 1.0000x reference)
#include <cuda_runtime.h>
#include <cuda_fp16.h>

typedef unsigned int u32;

#define H 512
#define W 512
#define PLANE (H * W)
#define NPLANES 64          // 32 pred + 32 true planes (channel 1 only)
#define RB 16               // output rows per warp
#define BANDS (H / RB)      // 32
#define STRIPS 2            // 256 cols per warp (8 cols/lane)
#define KSTEPS (RB + 4)     // 20 pipeline steps
#define NBLOCKS (NPLANES * BANDS * STRIPS / 4)   // 1024 blocks of 128 thr

#define PINF2 0x7C007C00u
#define NINF2 0xFC00FC00u

__device__ __half g_bufA[(size_t)NPLANES * PLANE];   // 32 MB
__device__ __half g_bufB[(size_t)NPLANES * PLANE];   // 32 MB
__device__ double g_acc[4];  // cross_pred, sum_pred, cross_true, sum_true

__device__ __forceinline__ u32 h2min(u32 a, u32 b) {
    __half2 r = __hmin2(*reinterpret_cast<__half2*>(&a),
                        *reinterpret_cast<__half2*>(&b));
    return *reinterpret_cast<u32*>(&r);
}
__device__ __forceinline__ u32 h2max(u32 a, u32 b) {
    __half2 r = __hmax2(*reinterpret_cast<__half2*>(&a),
                        *reinterpret_cast<__half2*>(&b));
    return *reinterpret_cast<u32*>(&r);
}
__device__ __forceinline__ u32 h2sub(u32 a, u32 b) {
    __half2 r = __hsub2(*reinterpret_cast<__half2*>(&a),
                        *reinterpret_cast<__half2*>(&b));
    return *reinterpret_cast<u32*>(&r);
}
__device__ __forceinline__ u32 h2add(u32 a, u32 b) {
    __half2 r = __hadd2(*reinterpret_cast<__half2*>(&a),
                        *reinterpret_cast<__half2*>(&b));
    return *reinterpret_cast<u32*>(&r);
}
__device__ __forceinline__ u32 pk(float lo, float hi) {
    __half2 r = __floats2half2_rn(lo, hi);
    return *reinterpret_cast<u32*>(&r);
}
__device__ __forceinline__ float2 up(u32 v) {
    return __half22float2(*reinterpret_cast<__half2*>(&v));
}
// (a.hi, b.lo) as (lo, hi)
__device__ __forceinline__ u32 mid(u32 a, u32 b) { return __byte_perm(a, b, 0x5432); }
__device__ __forceinline__ u32 swp(u32 a)        { return __byte_perm(a, a, 0x1032); }

// One soft-skeletonize iteration. Loads are issued into a raw register ring
// and only expanded (shuffle + halo splice) TWO steps later, so the LDG
// latency is covered by ~2 steps of ALU work instead of being serialized
// behind a dependent shuffle. Per-step compute is pure lane-local half2
// dataflow: vmin3 -> hmin(PRMT) -> hmax(PRMT) -> vmax3 -> z.
// MODE 0: fp32 strided input -> half. MODE 1: half -> half.
// MODE 2: half -> fused reduction (no store).
template <int MODE>
__global__ void __launch_bounds__(128) skel_kernel(
    const float* __restrict__ pred, const float* __restrict__ tru, int it)
{
    const int lane  = threadIdx.x & 31;
    const int gw    = blockIdx.x * 4 + (threadIdx.x >> 5);
    const int strip = gw & 1;
    const int band  = (gw >> 1) & (BANDS - 1);
    const int p     = gw >> 6;
    const int rbase = band * RB;
    const int cb    = strip * 256 + lane * 8;     // first owned column (halfs)
    const int b     = p & 31;

    const float* chan = (p < 32 ? pred : tru) + (size_t)(2 * b + 1) * PLANE;
    const float* oth  = (p < 32 ? tru : pred) + (size_t)(2 * b + 1) * PLANE;
    const __half* srcH = ((it & 1) ? g_bufA : g_bufB) + (size_t)p * PLANE;
    __half*       dstH = ((it & 1) ? g_bufB : g_bufA) + (size_t)p * PLANE;

    const bool eL = (lane == 0  && strip == 1);   // needs LDG halo (cols 254-255)
    const bool eR = (lane == 31 && strip == 0);   // needs LDG halo (cols 256-257)

    u32 raw[4][4];   // raw loaded rows ring; slot s holds row rbase-2+k with k&3==s
    u32 rawE[4];     // edge halo u32 per raw slot (lanes 0/31 of strip interior)
    u32 xr[4][6];    // expanded rows: [0]=cols cb-2..cb-1, [1..4]=cb..cb+7, [5]=cb+8..+9
    u32 hmr[4][4];   // horizontal-max-of-minpool rows ring
    u32 mc[2][4];    // minpool center ring for z
    float accC = 0.f, accS = 0.f;

#pragma unroll
    for (int i = 0; i < 6; ++i) { xr[2][i] = PINF2; xr[3][i] = PINF2; }

    // Issue loads only; nothing depends on them in this step.
    auto loadraw = [&](int r, int s) {
        u32 a1 = PINF2, a2 = PINF2, a3 = PINF2, a4 = PINF2, ae = PINF2;
        if ((unsigned)r < H) {
            if (MODE == 0) {
                const float* row = chan + (size_t)r * W + cb;
                float4 f0 = *reinterpret_cast<const float4*>(row);
                float4 f1 = *reinterpret_cast<const float4*>(row + 4);
                a1 = pk(f0.x, f0.y); a2 = pk(f0.z, f0.w);
                a3 = pk(f1.x, f1.y); a4 = pk(f1.z, f1.w);
                if (eL)      { float2 e = *reinterpret_cast<const float2*>(row - 2); ae = pk(e.x, e.y); }
                else if (eR) { float2 e = *reinterpret_cast<const float2*>(row + 8); ae = pk(e.x, e.y); }
            } else {
                const __half* row = srcH + (size_t)r * W + cb;
                uint4 v = *reinterpret_cast<const uint4*>(row);
                a1 = v.x; a2 = v.y; a3 = v.z; a4 = v.w;
                if (eL)      ae = *reinterpret_cast<const u32*>(row - 2);
                else if (eR) ae = *reinterpret_cast<const u32*>(row + 8);
            }
        }
        raw[s][0] = a1; raw[s][1] = a2; raw[s][2] = a3; raw[s][3] = a4;
        rawE[s] = ae;
    };

    // Shuffle + halo splice on data loaded 2 steps ago (already arrived).
    auto expand = [&](int s) {
        u32 a1 = raw[s][0], a4 = raw[s][3];
        u32 a0 = __shfl_up_sync(0xffffffffu, a4, 1);
        u32 a5 = __shfl_down_sync(0xffffffffu, a1, 1);
        if (lane == 0)  a0 = eL ? rawE[s] : PINF2;
        if (lane == 31) a5 = eR ? rawE[s] : PINF2;
        xr[s][0] = a0; xr[s][1] = a1; xr[s][2] = raw[s][1];
        xr[s][3] = raw[s][2]; xr[s][4] = a4; xr[s][5] = a5;
    };

    loadraw(rbase - 2, 0);
    loadraw(rbase - 1, 1);

#pragma unroll 1
    for (int kk = 0; kk < KSTEPS; kk += 4) {
        const bool OUT = (kk >= 4);
#pragma unroll
        for (int u = 0; u < 4; ++u) {
            const int k  = kk + u;
            const int s0 = (u + 2) & 3;   // row rbase-4+k (= output row o)
            const int s1 = (u + 3) & 3;   // row rbase-3+k
            const int s2 = u;             // row rbase-2+k
            const int sL = (u + 2) & 3;   // raw slot for load of row rbase+k

            if (k < KSTEPS - 2) loadraw(rbase + k, sL);  // depth-2 prefetch
            expand(s2);                                   // row rbase-2+k ready

            // vertical min over 3 x rows (6 u32 wide)
            u32 v[6];
#pragma unroll
            for (int i = 0; i < 6; ++i)
                v[i] = h2min(h2min(xr[s0][i], xr[s1][i]), xr[s2][i]);

            // horizontal min -> minpool row rm = rbase-3+k (ends half-garbage)
            u32 p01 = mid(v[0], v[1]), p12 = mid(v[1], v[2]), p23 = mid(v[2], v[3]);
            u32 p34 = mid(v[3], v[4]), p45 = mid(v[4], v[5]);
            u32 m0 = h2min(h2min(swp(v[0]), v[0]), p01);
            u32 m1 = h2min(h2min(p01, v[1]), p12);
            u32 m2 = h2min(h2min(p12, v[2]), p23);
            u32 m3 = h2min(h2min(p23, v[3]), p34);
            u32 m4 = h2min(h2min(p34, v[4]), p45);
            u32 m5 = h2min(h2min(p45, v[5]), swp(v[5]));

            const int rm = rbase - 3 + k;
            if ((unsigned)rm >= H) {      // maxpool pads -inf for OOB rows
                m0 = m1 = m2 = m3 = m4 = m5 = NINF2;
            }

            // horizontal max of minpool row (center 4 u32)
            u32 q01 = mid(m0, m1), q12 = mid(m1, m2), q23 = mid(m2, m3);
            u32 q34 = mid(m3, m4), q45 = mid(m4, m5);
            hmr[s2][0] = h2max(h2max(q01, m1), q12);
            hmr[s2][1] = h2max(h2max(q12, m2), q23);
            hmr[s2][2] = h2max(h2max(q23, m3), q34);
            hmr[s2][3] = h2max(h2max(q34, m4), q45);

            // stash minpool center for z (consumed next step)
            mc[k & 1][0] = m1; mc[k & 1][1] = m2;
            mc[k & 1][2] = m3; mc[k & 1][3] = m4;

            if (OUT) {
                const int o = rbase - 4 + k;
                // dil = vertical max of 3 hmax rows; z = relu(x - dil + m)
                // (dil >= m always since maxpool window contains center)
                u32 z[4];
#pragma unroll
                for (int i = 0; i < 4; ++i) {
                    u32 dil = h2max(h2max(hmr[s0][i], hmr[s1][i]), hmr[s2][i]);
                    z[i] = h2max(h2add(h2sub(xr[s0][i + 1], dil),
                                       mc[(k + 1) & 1][i]), 0u);
                }
                if (MODE == 2) {
                    const float* orow = oth + (size_t)o * W + cb;
                    float4 f0 = *reinterpret_cast<const float4*>(orow);
                    float4 f1 = *reinterpret_cast<const float4*>(orow + 4);
                    float2 a0 = up(z[0]), a1 = up(z[1]), a2 = up(z[2]), a3 = up(z[3]);
                    accC += a0.x * f0.x + a0.y * f0.y + a1.x * f0.z + a1.y * f0.w;
                    accC += a2.x * f1.x + a2.y * f1.y + a3.x * f1.z + a3.y * f1.w;
                    accS += (a0.x + a0.y) + (a1.x + a1.y)
                          + (a2.x + a2.y) + (a3.x + a3.y);
                } else {
                    uint4 st; st.x = z[0]; st.y = z[1]; st.z = z[2]; st.w = z[3];
                    *reinterpret_cast<uint4*>(dstH + (size_t)o * W + cb) = st;
                }
            }
        }
    }

    if (MODE == 2) {
#pragma unroll
        for (int s = 16; s; s >>= 1) {
            accC += __shfl_xor_sync(0xffffffffu, accC, s);
            accS += __shfl_xor_sync(0xffffffffu, accS, s);
        }
        __shared__ float sC[4], sS[4];
        const int wi = threadIdx.x >> 5;
        if (lane == 0) { sC[wi] = accC; sS[wi] = accS; }
        __syncthreads();
        if (threadIdx.x == 0) {
            double c = (double)sC[0] + sC[1] + sC[2] + sC[3];
            double s = (double)sS[0] + sS[1] + sS[2] + sS[3];
            const int base = (p < 32) ? 0 : 2;   // p constant within block
            atomicAdd(&g_acc[base],     c);
            atomicAdd(&g_acc[base + 1], s);
        }
    }
}

__global__ void zero_acc()
{
    if (threadIdx.x < 4) g_acc[threadIdx.x] = 0.0;
}

__global__ void finalize_kernel(float* out)
{
    const double SMOOTH = 1.0;
    double tprec = (g_acc[0] + SMOOTH) / (g_acc[1] + SMOOTH);
    double tsens = (g_acc[2] + SMOOTH) / (g_acc[3] + SMOOTH);
    out[0] = (float)(1.0 - 2.0 * (tprec * tsens) / (tprec + tsens));
}

extern "C" void kernel_launch(void* const* d_in, const int* in_sizes, int n_in,
                              void* d_out, int out_size)
{
    const float* pred = (const float*)d_in[0];
    const float* tru  = (const float*)d_in[1];

    zero_acc<<<1, 32>>>();
    skel_kernel<0><<<NBLOCKS, 128>>>(pred, tru, 0);
    for (int it = 1; it < 9; ++it)
        skel_kernel<1><<<NBLOCKS, 128>>>(pred, tru, it);
    skel_kernel<2><<<NBLOCKS, 128>>>(pred, tru, 9);
    finalize_kernel<<<1, 1>>>((float*)d_out);
}

// round 7
// speedup vs baseline: 1.1214x; 1.1214x over previous
#include <cuda_runtime.h>
#include <cuda_fp16.h>

typedef unsigned int u32;

#define H 512
#define W 512
#define PLANE (H * W)
#define NPLANES 64          // 32 pred + 32 true planes (channel 1 only)
#define RB 8                // output rows per warp
#define BANDS (H / RB)      // 64
#define KSTEPS (RB + 4)     // 12 pipeline steps
#define NBLOCKS (NPLANES * BANDS * 2 / 4)   // 2048 blocks of 128 thr

#define PINF2 0x7C007C00u
#define NINF2 0xFC00FC00u

__device__ __half g_bufA[(size_t)NPLANES * PLANE];   // 32 MB
__device__ __half g_bufB[(size_t)NPLANES * PLANE];   // 32 MB
__device__ double g_acc[4];  // cross_pred, sum_pred, cross_true, sum_true

__device__ __forceinline__ u32 h2min(u32 a, u32 b) {
    __half2 r = __hmin2(*reinterpret_cast<__half2*>(&a),
                        *reinterpret_cast<__half2*>(&b));
    return *reinterpret_cast<u32*>(&r);
}
__device__ __forceinline__ u32 h2max(u32 a, u32 b) {
    __half2 r = __hmax2(*reinterpret_cast<__half2*>(&a),
                        *reinterpret_cast<__half2*>(&b));
    return *reinterpret_cast<u32*>(&r);
}
__device__ __forceinline__ u32 h2sub(u32 a, u32 b) {
    __half2 r = __hsub2(*reinterpret_cast<__half2*>(&a),
                        *reinterpret_cast<__half2*>(&b));
    return *reinterpret_cast<u32*>(&r);
}
__device__ __forceinline__ u32 h2add(u32 a, u32 b) {
    __half2 r = __hadd2(*reinterpret_cast<__half2*>(&a),
                        *reinterpret_cast<__half2*>(&b));
    return *reinterpret_cast<u32*>(&r);
}
__device__ __forceinline__ u32 pk(float lo, float hi) {
    __half2 r = __floats2half2_rn(lo, hi);
    return *reinterpret_cast<u32*>(&r);
}
__device__ __forceinline__ float2 up(u32 v) {
    return __half22float2(*reinterpret_cast<__half2*>(&v));
}
// (a.hi, b.lo) as (lo, hi)
__device__ __forceinline__ u32 mid(u32 a, u32 b) { return __byte_perm(a, b, 0x5432); }
__device__ __forceinline__ u32 swp(u32 a)        { return __byte_perm(a, a, 0x1032); }

// One soft-skeletonize iteration. Row-streaming register pipeline with
// pair-based vertical reductions (vmin3(r) = min(pair(r-2,r-1), x_r)):
// eliminates deep row rings, cutting registers so RB=8 can run at high
// occupancy. Loads prefetched depth-2; full 12-step unroll.
// MODE 0: fp32 strided input -> half. MODE 1: half -> half.
// MODE 2: half -> fused reduction (no store).
template <int MODE>
__global__ void __launch_bounds__(128) skel_kernel(
    const float* __restrict__ pred, const float* __restrict__ tru, int it)
{
    const int lane  = threadIdx.x & 31;
    const int gw    = blockIdx.x * 4 + (threadIdx.x >> 5);
    const int strip = gw & 1;
    const int band  = (gw >> 1) & (BANDS - 1);
    const int p     = gw >> 7;
    const int rbase = band * RB;
    const int cb    = strip * 256 + lane * 8;     // first owned column (halfs)
    const int b     = p & 31;

    const float* chan = (p < 32 ? pred : tru) + (size_t)(2 * b + 1) * PLANE;
    const float* oth  = (p < 32 ? tru : pred) + (size_t)(2 * b + 1) * PLANE;
    const __half* srcH = ((it & 1) ? g_bufA : g_bufB) + (size_t)p * PLANE;
    __half*       dstH = ((it & 1) ? g_bufB : g_bufA) + (size_t)p * PLANE;

    const bool eL = (lane == 0  && strip == 1);   // needs LDG halo (cols 254-255)
    const bool eR = (lane == 31 && strip == 0);   // needs LDG halo (cols 256-257)

    u32 raw[4][4];   // raw loaded rows; row rbase+k lives in slot (k+2)&3
    u32 rawE[4];     // edge halo u32 per raw slot
    u32 x_prev[6];   // x row (expanded) from previous step
    u32 xpair[6];    // min(x_{r-2}, x_{r-1})
    u32 xc1[4], xc2[4];   // x center delayed 1 / 2 steps
    u32 mcp[4];      // minpool center from previous step
    u32 hmp[4];      // hm row from previous step
    u32 hmpair[4];   // max(hm_{o-1}, hm_o)
    float accC = 0.f, accS = 0.f;

#pragma unroll
    for (int i = 0; i < 6; ++i) { x_prev[i] = PINF2; xpair[i] = PINF2; }
#pragma unroll
    for (int i = 0; i < 4; ++i) {
        xc1[i] = 0u; xc2[i] = 0u; mcp[i] = 0u;
        hmp[i] = NINF2; hmpair[i] = NINF2;
    }

    // Issue loads only; nothing depends on them this step.
    auto loadraw = [&](int r, int s) {
        u32 a1 = PINF2, a2 = PINF2, a3 = PINF2, a4 = PINF2, ae = PINF2;
        if ((unsigned)r < H) {
            if (MODE == 0) {
                const float* row = chan + (size_t)r * W + cb;
                float4 f0 = *reinterpret_cast<const float4*>(row);
                float4 f1 = *reinterpret_cast<const float4*>(row + 4);
                a1 = pk(f0.x, f0.y); a2 = pk(f0.z, f0.w);
                a3 = pk(f1.x, f1.y); a4 = pk(f1.z, f1.w);
                if (eL)      { float2 e = *reinterpret_cast<const float2*>(row - 2); ae = pk(e.x, e.y); }
                else if (eR) { float2 e = *reinterpret_cast<const float2*>(row + 8); ae = pk(e.x, e.y); }
            } else {
                const __half* row = srcH + (size_t)r * W + cb;
                uint4 v = *reinterpret_cast<const uint4*>(row);
                a1 = v.x; a2 = v.y; a3 = v.z; a4 = v.w;
                if (eL)      ae = *reinterpret_cast<const u32*>(row - 2);
                else if (eR) ae = *reinterpret_cast<const u32*>(row + 8);
            }
        }
        raw[s][0] = a1; raw[s][1] = a2; raw[s][2] = a3; raw[s][3] = a4;
        rawE[s] = ae;
    };

    loadraw(rbase - 2, 0);
    loadraw(rbase - 1, 1);

#pragma unroll
    for (int k = 0; k < KSTEPS; ++k) {
        // depth-2 prefetch of row rbase+k into slot (k+2)&3
        if (k < KSTEPS - 2) loadraw(rbase + k, (k + 2) & 3);

        // expand row rx = rbase+k-2 (loaded 2 steps ago, slot k&3)
        u32 xn[6];
        {
            const int s = k & 3;
            u32 a1 = raw[s][0], a4 = raw[s][3];
            u32 a0 = __shfl_up_sync(0xffffffffu, a4, 1);
            u32 a5 = __shfl_down_sync(0xffffffffu, a1, 1);
            if (lane == 0)  a0 = eL ? rawE[s] : PINF2;
            if (lane == 31) a5 = eR ? rawE[s] : PINF2;
            xn[0] = a0; xn[1] = a1; xn[2] = raw[s][1];
            xn[3] = raw[s][2]; xn[4] = a4; xn[5] = a5;
        }

        // vertical min row rv = rbase+k-3 via pair
        u32 v[6];
#pragma unroll
        for (int i = 0; i < 6; ++i) v[i] = h2min(xpair[i], xn[i]);
#pragma unroll
        for (int i = 0; i < 6; ++i) { xpair[i] = h2min(x_prev[i], xn[i]); x_prev[i] = xn[i]; }

        // horizontal min -> minpool row rv
        u32 p01 = mid(v[0], v[1]), p12 = mid(v[1], v[2]), p23 = mid(v[2], v[3]);
        u32 p34 = mid(v[3], v[4]), p45 = mid(v[4], v[5]);
        u32 m0 = h2min(h2min(swp(v[0]), v[0]), p01);
        u32 m1 = h2min(h2min(p01, v[1]), p12);
        u32 m2 = h2min(h2min(p12, v[2]), p23);
        u32 m3 = h2min(h2min(p23, v[3]), p34);
        u32 m4 = h2min(h2min(p34, v[4]), p45);
        u32 m5 = h2min(h2min(p45, v[5]), swp(v[5]));

        const int rv = rbase + k - 3;
        if ((unsigned)rv >= H) {      // maxpool pads -inf for OOB rows
            m0 = m1 = m2 = m3 = m4 = m5 = NINF2;
        }

        // horizontal max of minpool (owned 4 u32)
        u32 q01 = mid(m0, m1), q12 = mid(m1, m2), q23 = mid(m2, m3);
        u32 q34 = mid(m3, m4), q45 = mid(m4, m5);
        u32 hv0 = h2max(h2max(q01, m1), q12);
        u32 hv1 = h2max(h2max(q12, m2), q23);
        u32 hv2 = h2max(h2max(q23, m3), q34);
        u32 hv3 = h2max(h2max(q34, m4), q45);

        if (k >= 4) {
            const int o = rbase + k - 4;   // output row
            // dil = max(hm_{o-1}, hm_o, hm_{o+1}) = max(hmpair, hv)
            // z = relu(x_o - dil + m_o)   (dil >= m always)
            u32 z0 = h2max(h2add(h2sub(xc2[0], h2max(hmpair[0], hv0)), mcp[0]), 0u);
            u32 z1 = h2max(h2add(h2sub(xc2[1], h2max(hmpair[1], hv1)), mcp[1]), 0u);
            u32 z2 = h2max(h2add(h2sub(xc2[2], h2max(hmpair[2], hv2)), mcp[2]), 0u);
            u32 z3 = h2max(h2add(h2sub(xc2[3], h2max(hmpair[3], hv3)), mcp[3]), 0u);

            if (MODE == 2) {
                const float* orow = oth + (size_t)o * W + cb;
                float4 f0 = *reinterpret_cast<const float4*>(orow);
                float4 f1 = *reinterpret_cast<const float4*>(orow + 4);
                float2 a0 = up(z0), a1 = up(z1), a2 = up(z2), a3 = up(z3);
                accC += a0.x * f0.x + a0.y * f0.y + a1.x * f0.z + a1.y * f0.w;
                accC += a2.x * f1.x + a2.y * f1.y + a3.x * f1.z + a3.y * f1.w;
                accS += (a0.x + a0.y) + (a1.x + a1.y)
                      + (a2.x + a2.y) + (a3.x + a3.y);
            } else {
                uint4 st; st.x = z0; st.y = z1; st.z = z2; st.w = z3;
                *reinterpret_cast<uint4*>(dstH + (size_t)o * W + cb) = st;
            }
        }

        // shift delayed state (renamed by full unroll)
        hmpair[0] = h2max(hmp[0], hv0); hmp[0] = hv0;
        hmpair[1] = h2max(hmp[1], hv1); hmp[1] = hv1;
        hmpair[2] = h2max(hmp[2], hv2); hmp[2] = hv2;
        hmpair[3] = h2max(hmp[3], hv3); hmp[3] = hv3;
        mcp[0] = m1; mcp[1] = m2; mcp[2] = m3; mcp[3] = m4;
        xc2[0] = xc1[0]; xc2[1] = xc1[1]; xc2[2] = xc1[2]; xc2[3] = xc1[3];
        xc1[0] = xn[1]; xc1[1] = xn[2]; xc1[2] = xn[3]; xc1[3] = xn[4];
    }

    if (MODE == 2) {
#pragma unroll
        for (int s = 16; s; s >>= 1) {
            accC += __shfl_xor_sync(0xffffffffu, accC, s);
            accS += __shfl_xor_sync(0xffffffffu, accS, s);
        }
        __shared__ float sC[4], sS[4];
        const int wi = threadIdx.x >> 5;
        if (lane == 0) { sC[wi] = accC; sS[wi] = accS; }
        __syncthreads();
        if (threadIdx.x == 0) {
            double c = (double)sC[0] + sC[1] + sC[2] + sC[3];
            double s = (double)sS[0] + sS[1] + sS[2] + sS[3];
            const int base = (p < 32) ? 0 : 2;   // p constant within block
            atomicAdd(&g_acc[base],     c);
            atomicAdd(&g_acc[base + 1], s);
        }
    }
}

__global__ void zero_acc()
{
    if (threadIdx.x < 4) g_acc[threadIdx.x] = 0.0;
}

__global__ void finalize_kernel(float* out)
{
    const double SMOOTH = 1.0;
    double tprec = (g_acc[0] + SMOOTH) / (g_acc[1] + SMOOTH);
    double tsens = (g_acc[2] + SMOOTH) / (g_acc[3] + SMOOTH);
    out[0] = (float)(1.0 - 2.0 * (tprec * tsens) / (tprec + tsens));
}

extern "C" void kernel_launch(void* const* d_in, const int* in_sizes, int n_in,
                              void* d_out, int out_size)
{
    const float* pred = (const float*)d_in[0];
    const float* tru  = (const float*)d_in[1];

    zero_acc<<<1, 32>>>();
    skel_kernel<0><<<NBLOCKS, 128>>>(pred, tru, 0);
    for (int it = 1; it < 9; ++it)
        skel_kernel<1><<<NBLOCKS, 128>>>(pred, tru, it);
    skel_kernel<2><<<NBLOCKS, 128>>>(pred, tru, 9);
    finalize_kernel<<<1, 1>>>((float*)d_out);
}